// round 6
// baseline (speedup 1.0000x reference)
#include <cuda_runtime.h>
#include <cstddef>

#define NEG_INFF (-9.0e15f)
#define BN_EPS 1e-5f

// ---------------- device-global weight scratch (allocation-free) ----------------
__device__ float g_WqkvT[128 * 384];   // [c][col]: col 0..127 = q (h*8+e), 128..255 = k, 256..383 = v
__device__ float g_WcT[256 * 256];     // [c][o]   = conv_w[o][c]

// ---------------- prep: transpose weights for coalesced access ----------------
__global__ void prep_kernel(const float* __restrict__ Wq, const float* __restrict__ Wk,
                            const float* __restrict__ Wv, const float* __restrict__ convw) {
    int i = blockIdx.x * blockDim.x + threadIdx.x;
    if (i < 128 * 384) {
        int c = i / 384, col = i - c * 384;
        int part = col >> 7;          // 0=q 1=k 2=v
        int hc = col & 127;           // h*8+e
        int h = hc >> 3, e = hc & 7;
        const float* W = (part == 0) ? Wq : (part == 1 ? Wk : Wv);
        g_WqkvT[i] = W[h * 1024 + c * 8 + e];     // Wq[h][c][e], shape (16,128,8)
    } else {
        int j = i - 128 * 384;
        if (j < 256 * 256) {
            int c = j / 256, o = j - c * 256;
            g_WcT[j] = convw[o * 256 + c];
        }
    }
}

// ---------------- fused main kernel ----------------
// smem layout (floats):
#define XS_OFF   0                 // Xs[136][129]
#define AO_OFF   17544             // Ao[136][129]
#define SCR_OFF  35088             // union: {qs[136][33], ks, vs, maskb[4][289]} | {Ys[64][137]}
#define QS_OFF   (SCR_OFF)
#define KS_OFF   (SCR_OFF + 4488)
#define VS_OFF   (SCR_OFF + 8976)
#define MB_OFF   (SCR_OFF + 13464)
#define YS_OFF   (SCR_OFF)
#define BNS_OFF  49776             // bn scale[256]
#define BNB_OFF  50032             // bn shift[256]
#define SMEM_FLOATS 50288
#define SMEM_BYTES  (SMEM_FLOATS * 4)   // 201152

extern __shared__ float sm[];

__global__ void __launch_bounds__(256, 1)
gab_kernel(const float* __restrict__ x, const float* __restrict__ adj,
           const float* __restrict__ adj2,
           const float* __restrict__ bng, const float* __restrict__ bnbv,
           const float* __restrict__ bnm, const float* __restrict__ bnv,
           float* __restrict__ out) {
    const int b  = blockIdx.x >> 6;        // 0..31
    const int tb = blockIdx.x & 63;        // 0..63
    const int t0 = tb * 8;
    const int tid  = threadIdx.x;
    const int lane = tid & 31;
    const int wid  = tid >> 5;
    const int o32  = tid & 31;             // column-trip within warp
    const int tt   = tid >> 5;             // token tile (17 tokens each), 0..7

    // ---- Phase A: load X tile, transposed: Xs[tok][d] ----
    // x[b][d][t][n] = x[b*128*8704 + d*8704 + (t*17+n)]
    {
        const float* xb = x + (size_t)b * 128 * 8704 + (size_t)t0 * 17;
        for (int d = wid; d < 128; d += 8) {
            const float* src = xb + (size_t)d * 8704;
            for (int tok = lane; tok < 136; tok += 32)
                sm[XS_OFF + tok * 129 + d] = src[tok];
        }
    }
    // ---- BN fold ----
    {
        float sc = bng[tid] * rsqrtf(bnv[tid] + BN_EPS);
        sm[BNS_OFF + tid] = sc;
        sm[BNB_OFF + tid] = bnbv[tid] - bnm[tid] * sc;
    }
    __syncthreads();

    const float inv_s = 0.3535533905932738f;   // 1/sqrt(8)

    // ---- Phase B: 4 head-groups of 4 heads: QKV GEMM + attention ----
    for (int g = 0; g < 4; ++g) {
        // mask bias for the 4 heads of this group
        for (int idx = tid; idx < 4 * 289; idx += 256) {
            int hl = idx / 289, r = idx - hl * 289;
            int n = r / 17, m = r - n * 17;
            int h = g * 4 + hl;
            float a = adj[n * 17 + m]
                    + 0.5f * (adj2[h * 289 + n * 17 + m] + adj2[h * 289 + m * 17 + n]);
            sm[MB_OFF + idx] = (a > 0.0f) ? 0.0f : NEG_INFF;
        }

        // QKV: each thread computes (17 tokens) x (one q col, one k col, one v col)
        float aq[17], ak[17], av[17];
#pragma unroll
        for (int i = 0; i < 17; ++i) { aq[i] = 0.f; ak[i] = 0.f; av[i] = 0.f; }
        {
            const float* wptr = g_WqkvT + g * 32 + o32;
            const float* xrow = sm + XS_OFF + tt * 17 * 129;
#pragma unroll 4
            for (int c = 0; c < 128; ++c) {
                float wq = __ldg(wptr + c * 384);
                float wk = __ldg(wptr + c * 384 + 128);
                float wv = __ldg(wptr + c * 384 + 256);
#pragma unroll
                for (int i = 0; i < 17; ++i) {
                    float xv = xrow[i * 129 + c];
                    aq[i] = fmaf(xv, wq, aq[i]);
                    ak[i] = fmaf(xv, wk, ak[i]);
                    av[i] = fmaf(xv, wv, av[i]);
                }
            }
        }
#pragma unroll
        for (int i = 0; i < 17; ++i) {
            int tok = tt * 17 + i;
            sm[QS_OFF + tok * 33 + o32] = aq[i];
            sm[KS_OFF + tok * 33 + o32] = ak[i];
            sm[VS_OFF + tok * 33 + o32] = av[i];
        }
        __syncthreads();

        // Attention: one row per (tok, head-in-group): 544 rows
        for (int r = tid; r < 544; r += 256) {
            int hl  = r / 136;
            int tok = r - hl * 136;
            int tl  = tok / 17;
            int n   = tok - tl * 17;
            const float* qp = sm + QS_OFF + tok * 33 + hl * 8;
            const float* kb = sm + KS_OFF + tl * 17 * 33 + hl * 8;
            const float* vb = sm + VS_OFF + tl * 17 * 33 + hl * 8;
            const float* mb = sm + MB_OFF + hl * 289 + n * 17;
            float qv[8];
#pragma unroll
            for (int e = 0; e < 8; ++e) qv[e] = qp[e];
            float ev[17];
            float mx = -3.4e38f;
#pragma unroll
            for (int m = 0; m < 17; ++m) {
                const float* kp = kb + m * 33;
                float d0 = 0.f;
#pragma unroll
                for (int e = 0; e < 8; ++e) d0 = fmaf(qv[e], kp[e], d0);
                ev[m] = fmaf(d0, inv_s, mb[m]);
                mx = fmaxf(mx, ev[m]);
            }
            float s = 0.f;
#pragma unroll
            for (int m = 0; m < 17; ++m) { ev[m] = expf(ev[m] - mx); s += ev[m]; }
            float inv = 1.0f / s;
            float acc[8];
#pragma unroll
            for (int e = 0; e < 8; ++e) acc[e] = 0.f;
#pragma unroll
            for (int m = 0; m < 17; ++m) {
                const float* vp = vb + m * 33;
                float pm = ev[m];
#pragma unroll
                for (int e = 0; e < 8; ++e) acc[e] = fmaf(pm, vp[e], acc[e]);
            }
            float* ao = sm + AO_OFF + tok * 129 + g * 32 + hl * 8;
#pragma unroll
            for (int e = 0; e < 8; ++e) ao[e] = acc[e] * inv;
        }
        __syncthreads();   // qs/ks/vs reusable next group; Ao complete after g=3
    }

    // ---- Phase C: conv1x1 (cat = [Xs | Ao]) + BN + ReLU, in 4 chunks of 64 outputs ----
    for (int p = 0; p < 4; ++p) {
        const int ob = p * 64;
        float acc0[17], acc1[17];
#pragma unroll
        for (int i = 0; i < 17; ++i) { acc0[i] = 0.f; acc1[i] = 0.f; }
        const float* xrow = sm + XS_OFF + tt * 17 * 129;
        const float* arow = sm + AO_OFF + tt * 17 * 129;
        const float* w0 = g_WcT + ob + o32;
#pragma unroll 4
        for (int c = 0; c < 128; ++c) {
            float wa = __ldg(w0 + c * 256);
            float wb = __ldg(w0 + c * 256 + 32);
#pragma unroll
            for (int i = 0; i < 17; ++i) {
                float cv = xrow[i * 129 + c];
                acc0[i] = fmaf(cv, wa, acc0[i]);
                acc1[i] = fmaf(cv, wb, acc1[i]);
            }
        }
        const float* w1 = w0 + 128 * 256;
#pragma unroll 4
        for (int c = 0; c < 128; ++c) {
            float wa = __ldg(w1 + c * 256);
            float wb = __ldg(w1 + c * 256 + 32);
#pragma unroll
            for (int i = 0; i < 17; ++i) {
                float cv = arow[i * 129 + c];
                acc0[i] = fmaf(cv, wa, acc0[i]);
                acc1[i] = fmaf(cv, wb, acc1[i]);
            }
        }
        // BN + ReLU into staging buffer Ys[64][137]
        {
            int oa = ob + o32, oc = oa + 32;
            float s0 = sm[BNS_OFF + oa], h0 = sm[BNB_OFF + oa];
            float s1 = sm[BNS_OFF + oc], h1 = sm[BNB_OFF + oc];
#pragma unroll
            for (int i = 0; i < 17; ++i) {
                int tok = tt * 17 + i;
                sm[YS_OFF + o32 * 137 + tok]        = fmaxf(fmaf(acc0[i], s0, h0), 0.0f);
                sm[YS_OFF + (o32 + 32) * 137 + tok] = fmaxf(fmaf(acc1[i], s1, h1), 0.0f);
            }
        }
        __syncthreads();
        // coalesced store: out[b][o][t][n] = out[(b*256+o)*8704 + t*17+n]
        {
            float* ob_ptr = out + (size_t)(b * 256 + ob) * 8704 + (size_t)t0 * 17;
            for (int idx = tid; idx < 64 * 136; idx += 256) {
                int ol = idx / 136;
                int tok = idx - ol * 136;
                ob_ptr[(size_t)ol * 8704 + tok] = sm[YS_OFF + ol * 137 + tok];
            }
        }
        __syncthreads();
    }
}

// ---------------- launch ----------------
extern "C" void kernel_launch(void* const* d_in, const int* in_sizes, int n_in,
                              void* d_out, int out_size) {
    const float* x      = (const float*)d_in[0];
    const float* adj    = (const float*)d_in[1];
    const float* Wq     = (const float*)d_in[2];
    const float* Wk     = (const float*)d_in[3];
    const float* Wv     = (const float*)d_in[4];
    const float* adj2   = (const float*)d_in[5];
    const float* convw  = (const float*)d_in[6];
    const float* bng    = (const float*)d_in[7];
    const float* bnb    = (const float*)d_in[8];
    const float* bnm    = (const float*)d_in[9];
    const float* bnv    = (const float*)d_in[10];
    float* out = (float*)d_out;

    cudaFuncSetAttribute(gab_kernel, cudaFuncAttributeMaxDynamicSharedMemorySize, SMEM_BYTES);

    prep_kernel<<<(128 * 384 + 256 * 256 + 255) / 256, 256>>>(Wq, Wk, Wv, convw);
    gab_kernel<<<2048, 256, SMEM_BYTES>>>(x, adj, adj2, bng, bnb, bnm, bnv, out);
}

// round 7
// speedup vs baseline: 1.0550x; 1.0550x over previous
#include <cuda_runtime.h>
#include <cstddef>

#define NEG_INFF (-9.0e15f)
#define BN_EPS 1e-5f

// ---------------- device-global weight scratch (allocation-free) ----------------
// g_Wqkv2[col][c]: col 0..127 = q (h*8+e), 128..255 = k, 256..383 = v; row-major over c (128)
__device__ float g_Wqkv2[384 * 128];

// ---------------- prep: repack qkv weights to [col][c] ----------------
__global__ void prep_kernel(const float* __restrict__ Wq, const float* __restrict__ Wk,
                            const float* __restrict__ Wv) {
    int i = blockIdx.x * blockDim.x + threadIdx.x;   // i over 384*128
    if (i < 384 * 128) {
        int col = i >> 7;          // 0..383
        int c   = i & 127;
        int part = col >> 7;       // 0=q 1=k 2=v
        int hc = col & 127;        // h*8+e
        int h = hc >> 3, e = hc & 7;
        const float* W = (part == 0) ? Wq : (part == 1 ? Wk : Wv);
        g_Wqkv2[i] = W[h * 1024 + c * 8 + e];   // W[h][c][e], shape (16,128,8)
    }
}

// ---------------- fused main kernel ----------------
// smem layout (floats):
#define XSTR 132
#define XS_OFF   0                    // Xs[136][132]
#define AO_OFF   17952                // Ao[136][132]
#define SCR_OFF  35904
#define QSTR 36
#define QS_OFF   (SCR_OFF)            // qs[136][36]
#define KS_OFF   (SCR_OFF + 4896)
#define VS_OFF   (SCR_OFF + 9792)
#define MB_OFF   (SCR_OFF + 14688)    // mask[4][289]
#define YS_OFF   (SCR_OFF)            // union: Ys[64][137] (phase C only)
#define BNS_OFF  51748
#define BNB_OFF  52004
#define SMEM_FLOATS 52260
#define SMEM_BYTES  (SMEM_FLOATS * 4)   // 209040

extern __shared__ float sm[];

__global__ void __launch_bounds__(256, 1)
gab_kernel(const float* __restrict__ x, const float* __restrict__ adj,
           const float* __restrict__ adj2, const float* __restrict__ convw,
           const float* __restrict__ bng, const float* __restrict__ bnbv,
           const float* __restrict__ bnm, const float* __restrict__ bnv,
           float* __restrict__ out) {
    const int b  = blockIdx.x >> 6;        // 0..31
    const int tb = blockIdx.x & 63;        // 0..63
    const int t0 = tb * 8;
    const int tid  = threadIdx.x;
    const int lane = tid & 31;
    const int wid  = tid >> 5;
    const int o32  = tid & 31;
    const int tt   = tid >> 5;             // token tile (17 tokens each), 0..7

    // ---- Phase A: load X tile transposed: Xs[tok][d], STS.128 over 4 d's ----
    // x[b][d][t][n] = x[b*128*8704 + d*8704 + (t*17+n)]
    {
        const float* xb = x + (size_t)b * 128 * 8704 + (size_t)t0 * 17;
        for (int d4 = wid; d4 < 32; d4 += 8) {
            const float* s0 = xb + (size_t)(d4 * 4 + 0) * 8704;
            const float* s1 = xb + (size_t)(d4 * 4 + 1) * 8704;
            const float* s2 = xb + (size_t)(d4 * 4 + 2) * 8704;
            const float* s3 = xb + (size_t)(d4 * 4 + 3) * 8704;
            for (int tok = lane; tok < 136; tok += 32) {
                float4 v;
                v.x = s0[tok]; v.y = s1[tok]; v.z = s2[tok]; v.w = s3[tok];
                *reinterpret_cast<float4*>(sm + XS_OFF + tok * XSTR + d4 * 4) = v;
            }
        }
    }
    // ---- BN fold ----
    {
        float sc = bng[tid] * rsqrtf(bnv[tid] + BN_EPS);
        sm[BNS_OFF + tid] = sc;
        sm[BNB_OFF + tid] = bnbv[tid] - bnm[tid] * sc;
    }
    __syncthreads();

    const float inv_s = 0.3535533905932738f;   // 1/sqrt(8)

    // ---- Phase B: 4 head-groups of 4 heads: QKV GEMM + attention ----
    for (int g = 0; g < 4; ++g) {
        // mask bias for the 4 heads of this group
        for (int idx = tid; idx < 4 * 289; idx += 256) {
            int hl = idx / 289, r = idx - hl * 289;
            int n = r / 17, m = r - n * 17;
            int h = g * 4 + hl;
            float a = 0.5f * (adj[n * 17 + m] + adj[m * 17 + n])
                    + 0.5f * (adj2[h * 289 + n * 17 + m] + adj2[h * 289 + m * 17 + n]);
            sm[MB_OFF + idx] = (a > 0.0f) ? 0.0f : NEG_INFF;
        }

        // QKV GEMM: thread = (17 tokens) x (one q col, one k col, one v col)
        float aq[17], ak[17], av[17];
#pragma unroll
        for (int i = 0; i < 17; ++i) { aq[i] = 0.f; ak[i] = 0.f; av[i] = 0.f; }
        {
            const float* pq = g_Wqkv2 + (g * 32 + o32) * 128;
            const float* pk = pq + 128 * 128;
            const float* pv = pq + 256 * 128;
            const float* xrow = sm + XS_OFF + tt * 17 * XSTR;
            float4 wq = __ldg(reinterpret_cast<const float4*>(pq));
            float4 wk = __ldg(reinterpret_cast<const float4*>(pk));
            float4 wv = __ldg(reinterpret_cast<const float4*>(pv));
#pragma unroll 4
            for (int c4 = 0; c4 < 32; ++c4) {
                float4 cq = wq, ck = wk, cv = wv;
                if (c4 < 31) {
                    wq = __ldg(reinterpret_cast<const float4*>(pq + (c4 + 1) * 4));
                    wk = __ldg(reinterpret_cast<const float4*>(pk + (c4 + 1) * 4));
                    wv = __ldg(reinterpret_cast<const float4*>(pv + (c4 + 1) * 4));
                }
#pragma unroll
                for (int i = 0; i < 17; ++i) {
                    float4 xv = *reinterpret_cast<const float4*>(xrow + i * XSTR + c4 * 4);
                    aq[i] = fmaf(xv.x, cq.x, aq[i]); aq[i] = fmaf(xv.y, cq.y, aq[i]);
                    aq[i] = fmaf(xv.z, cq.z, aq[i]); aq[i] = fmaf(xv.w, cq.w, aq[i]);
                    ak[i] = fmaf(xv.x, ck.x, ak[i]); ak[i] = fmaf(xv.y, ck.y, ak[i]);
                    ak[i] = fmaf(xv.z, ck.z, ak[i]); ak[i] = fmaf(xv.w, ck.w, ak[i]);
                    av[i] = fmaf(xv.x, cv.x, av[i]); av[i] = fmaf(xv.y, cv.y, av[i]);
                    av[i] = fmaf(xv.z, cv.z, av[i]); av[i] = fmaf(xv.w, cv.w, av[i]);
                }
            }
        }
#pragma unroll
        for (int i = 0; i < 17; ++i) {
            int tok = tt * 17 + i;
            sm[QS_OFF + tok * QSTR + o32] = aq[i];
            sm[KS_OFF + tok * QSTR + o32] = ak[i];
            sm[VS_OFF + tok * QSTR + o32] = av[i];
        }
        __syncthreads();

        // Attention: one row per (tok, head-in-group): 544 rows
        for (int r = tid; r < 544; r += 256) {
            int hl  = r / 136;
            int tok = r - hl * 136;
            int tl  = tok / 17;
            int n   = tok - tl * 17;
            const float* qp = sm + QS_OFF + tok * QSTR + hl * 8;
            const float* kb = sm + KS_OFF + tl * 17 * QSTR + hl * 8;
            const float* vb = sm + VS_OFF + tl * 17 * QSTR + hl * 8;
            const float* mb = sm + MB_OFF + hl * 289 + n * 17;
            float4 q0 = *reinterpret_cast<const float4*>(qp);
            float4 q1 = *reinterpret_cast<const float4*>(qp + 4);
            float ev[17];
            float mx = -3.4e38f;
#pragma unroll
            for (int m = 0; m < 17; ++m) {
                const float* kp = kb + m * QSTR;
                float4 k0 = *reinterpret_cast<const float4*>(kp);
                float4 k1 = *reinterpret_cast<const float4*>(kp + 4);
                float d0 = q0.x * k0.x;
                d0 = fmaf(q0.y, k0.y, d0); d0 = fmaf(q0.z, k0.z, d0); d0 = fmaf(q0.w, k0.w, d0);
                d0 = fmaf(q1.x, k1.x, d0); d0 = fmaf(q1.y, k1.y, d0);
                d0 = fmaf(q1.z, k1.z, d0); d0 = fmaf(q1.w, k1.w, d0);
                ev[m] = fmaf(d0, inv_s, mb[m]);
                mx = fmaxf(mx, ev[m]);
            }
            float s = 0.f;
#pragma unroll
            for (int m = 0; m < 17; ++m) { ev[m] = __expf(ev[m] - mx); s += ev[m]; }
            float inv = __fdividef(1.0f, s);
            float4 a0 = make_float4(0.f, 0.f, 0.f, 0.f);
            float4 a1 = make_float4(0.f, 0.f, 0.f, 0.f);
#pragma unroll
            for (int m = 0; m < 17; ++m) {
                const float* vp = vb + m * QSTR;
                float4 v0 = *reinterpret_cast<const float4*>(vp);
                float4 v1 = *reinterpret_cast<const float4*>(vp + 4);
                float pm = ev[m];
                a0.x = fmaf(pm, v0.x, a0.x); a0.y = fmaf(pm, v0.y, a0.y);
                a0.z = fmaf(pm, v0.z, a0.z); a0.w = fmaf(pm, v0.w, a0.w);
                a1.x = fmaf(pm, v1.x, a1.x); a1.y = fmaf(pm, v1.y, a1.y);
                a1.z = fmaf(pm, v1.z, a1.z); a1.w = fmaf(pm, v1.w, a1.w);
            }
            a0.x *= inv; a0.y *= inv; a0.z *= inv; a0.w *= inv;
            a1.x *= inv; a1.y *= inv; a1.z *= inv; a1.w *= inv;
            float* ao = sm + AO_OFF + tok * XSTR + g * 32 + hl * 8;
            *reinterpret_cast<float4*>(ao) = a0;
            *reinterpret_cast<float4*>(ao + 4) = a1;
        }
        __syncthreads();
    }

    // ---- Phase C: conv1x1 (cat = [Xs | Ao]) + BN + ReLU, 4 chunks of 64 outputs ----
    for (int p = 0; p < 4; ++p) {
        const int ob = p * 64;
        float acc0[17], acc1[17];
#pragma unroll
        for (int i = 0; i < 17; ++i) { acc0[i] = 0.f; acc1[i] = 0.f; }
        const float* xrow = sm + XS_OFF + tt * 17 * XSTR;
        const float* arow = sm + AO_OFF + tt * 17 * XSTR;
        // first half: channels 0..127 (x part)
        {
            const float* w0 = convw + (size_t)(ob + o32) * 256;
            const float* w1 = w0 + 32 * 256;
            float4 wa = __ldg(reinterpret_cast<const float4*>(w0));
            float4 wb = __ldg(reinterpret_cast<const float4*>(w1));
#pragma unroll 4
            for (int c4 = 0; c4 < 32; ++c4) {
                float4 ca = wa, cb = wb;
                if (c4 < 31) {
                    wa = __ldg(reinterpret_cast<const float4*>(w0 + (c4 + 1) * 4));
                    wb = __ldg(reinterpret_cast<const float4*>(w1 + (c4 + 1) * 4));
                }
#pragma unroll
                for (int i = 0; i < 17; ++i) {
                    float4 xv = *reinterpret_cast<const float4*>(xrow + i * XSTR + c4 * 4);
                    acc0[i] = fmaf(xv.x, ca.x, acc0[i]); acc0[i] = fmaf(xv.y, ca.y, acc0[i]);
                    acc0[i] = fmaf(xv.z, ca.z, acc0[i]); acc0[i] = fmaf(xv.w, ca.w, acc0[i]);
                    acc1[i] = fmaf(xv.x, cb.x, acc1[i]); acc1[i] = fmaf(xv.y, cb.y, acc1[i]);
                    acc1[i] = fmaf(xv.z, cb.z, acc1[i]); acc1[i] = fmaf(xv.w, cb.w, acc1[i]);
                }
            }
        }
        // second half: channels 128..255 (attention out part)
        {
            const float* w0 = convw + (size_t)(ob + o32) * 256 + 128;
            const float* w1 = w0 + 32 * 256;
            float4 wa = __ldg(reinterpret_cast<const float4*>(w0));
            float4 wb = __ldg(reinterpret_cast<const float4*>(w1));
#pragma unroll 4
            for (int c4 = 0; c4 < 32; ++c4) {
                float4 ca = wa, cb = wb;
                if (c4 < 31) {
                    wa = __ldg(reinterpret_cast<const float4*>(w0 + (c4 + 1) * 4));
                    wb = __ldg(reinterpret_cast<const float4*>(w1 + (c4 + 1) * 4));
                }
#pragma unroll
                for (int i = 0; i < 17; ++i) {
                    float4 xv = *reinterpret_cast<const float4*>(arow + i * XSTR + c4 * 4);
                    acc0[i] = fmaf(xv.x, ca.x, acc0[i]); acc0[i] = fmaf(xv.y, ca.y, acc0[i]);
                    acc0[i] = fmaf(xv.z, ca.z, acc0[i]); acc0[i] = fmaf(xv.w, ca.w, acc0[i]);
                    acc1[i] = fmaf(xv.x, cb.x, acc1[i]); acc1[i] = fmaf(xv.y, cb.y, acc1[i]);
                    acc1[i] = fmaf(xv.z, cb.z, acc1[i]); acc1[i] = fmaf(xv.w, cb.w, acc1[i]);
                }
            }
        }
        __syncthreads();   // protect YS (overlaps qs region) until attention done / prev stores read
        // BN + ReLU into staging buffer Ys[64][137]
        {
            int oa = ob + o32, oc = oa + 32;
            float s0 = sm[BNS_OFF + oa], h0 = sm[BNB_OFF + oa];
            float s1 = sm[BNS_OFF + oc], h1 = sm[BNB_OFF + oc];
#pragma unroll
            for (int i = 0; i < 17; ++i) {
                int tok = tt * 17 + i;
                sm[YS_OFF + o32 * 137 + tok]        = fmaxf(fmaf(acc0[i], s0, h0), 0.0f);
                sm[YS_OFF + (o32 + 32) * 137 + tok] = fmaxf(fmaf(acc1[i], s1, h1), 0.0f);
            }
        }
        __syncthreads();
        // coalesced store: out[b][o][t][n] = out[(b*256+o)*8704 + t*17+n]
        {
            float* ob_ptr = out + (size_t)(b * 256 + ob) * 8704 + (size_t)t0 * 17;
            for (int idx = tid; idx < 64 * 136; idx += 256) {
                int ol = idx / 136;
                int tok = idx - ol * 136;
                ob_ptr[(size_t)ol * 8704 + tok] = sm[YS_OFF + ol * 137 + tok];
            }
        }
        __syncthreads();
    }
}

// ---------------- launch ----------------
extern "C" void kernel_launch(void* const* d_in, const int* in_sizes, int n_in,
                              void* d_out, int out_size) {
    const float* x      = (const float*)d_in[0];
    const float* adj    = (const float*)d_in[1];
    const float* Wq     = (const float*)d_in[2];
    const float* Wk     = (const float*)d_in[3];
    const float* Wv     = (const float*)d_in[4];
    const float* adj2   = (const float*)d_in[5];
    const float* convw  = (const float*)d_in[6];
    const float* bng    = (const float*)d_in[7];
    const float* bnb    = (const float*)d_in[8];
    const float* bnm    = (const float*)d_in[9];
    const float* bnv    = (const float*)d_in[10];
    float* out = (float*)d_out;

    cudaFuncSetAttribute(gab_kernel, cudaFuncAttributeMaxDynamicSharedMemorySize, SMEM_BYTES);

    prep_kernel<<<(384 * 128 + 255) / 256, 256>>>(Wq, Wk, Wv);
    gab_kernel<<<2048, 256, SMEM_BYTES>>>(x, adj, adj2, convw, bng, bnb, bnm, bnv, out);
}

// round 8
// speedup vs baseline: 1.5986x; 1.5153x over previous
#include <cuda_runtime.h>
#include <cstddef>

#define NEG_INFF (-9.0e15f)
#define BN_EPS 1e-5f

// ---------------- device-global weight scratch (allocation-free) ----------------
// g_Wqkv3[g][c][96]: for head-group g (4 heads), channel c, 96 cols = {q:32 | k:32 | v:32}
__device__ float g_Wqkv3[4 * 128 * 96];
// g_WcT[c][o] = conv_w[o][c]
__device__ float g_WcT[256 * 256];

// ---------------- prep: repack weights ----------------
__global__ void prep_kernel(const float* __restrict__ Wq, const float* __restrict__ Wk,
                            const float* __restrict__ Wv, const float* __restrict__ convw) {
    int i = blockIdx.x * blockDim.x + threadIdx.x;
    if (i < 4 * 128 * 96) {
        int g = i / (128 * 96);
        int r = i - g * (128 * 96);
        int c = r / 96, col = r - c * 96;
        int part = col >> 5;          // 0=q 1=k 2=v
        int o = col & 31;             // col within group
        int gc = g * 32 + o;          // global head-col 0..127
        int h = gc >> 3, e = gc & 7;
        const float* W = (part == 0) ? Wq : (part == 1 ? Wk : Wv);
        g_Wqkv3[i] = W[h * 1024 + c * 8 + e];   // W[h][c][e], shape (16,128,8)
    } else {
        int j = i - 4 * 128 * 96;
        if (j < 256 * 256) {
            int c = j >> 8, o = j & 255;
            g_WcT[j] = convw[o * 256 + c];
        }
    }
}

// ---------------- fused main kernel ----------------
// smem layout (floats):
#define XSTR 132
#define XS_OFF   0                    // Xs[136][132]
#define AO_OFF   17952                // Ao[136][132]
#define SCR_OFF  35904
#define QSTR 36
#define WS_OFF   (SCR_OFF)            // union A: W tile (qkv: 12288 | conv: 8192)
#define QS_OFF   (SCR_OFF)            // union B: qs[136][36]
#define KS_OFF   (SCR_OFF + 4896)
#define VS_OFF   (SCR_OFF + 9792)
#define MB_OFF   (SCR_OFF + 14688)    // mask[4][289] (outside both unions)
#define YS_OFF   (SCR_OFF)            // union C: Ys[64][137] (phase C epilogue)
#define BNS_OFF  51748
#define BNB_OFF  52004
#define SMEM_FLOATS 52260
#define SMEM_BYTES  (SMEM_FLOATS * 4)   // 209040

extern __shared__ float sm[];

__global__ void __launch_bounds__(256, 1)
gab_kernel(const float* __restrict__ x, const float* __restrict__ adj,
           const float* __restrict__ adj2,
           const float* __restrict__ bng, const float* __restrict__ bnbv,
           const float* __restrict__ bnm, const float* __restrict__ bnv,
           float* __restrict__ out) {
    const int b  = blockIdx.x >> 6;        // 0..31
    const int tb = blockIdx.x & 63;        // 0..63
    const int t0 = tb * 8;
    const int tid  = threadIdx.x;
    const int lane = tid & 31;
    const int wid  = tid >> 5;
    const int o32  = tid & 31;
    const int tt   = tid >> 5;             // token tile (17 tokens each), 0..7

    // ---- Phase A: load X tile transposed: Xs[tok][d] ----
    {
        const float* xb = x + (size_t)b * 128 * 8704 + (size_t)t0 * 17;
        for (int d4 = wid; d4 < 32; d4 += 8) {
            const float* s0 = xb + (size_t)(d4 * 4 + 0) * 8704;
            const float* s1 = xb + (size_t)(d4 * 4 + 1) * 8704;
            const float* s2 = xb + (size_t)(d4 * 4 + 2) * 8704;
            const float* s3 = xb + (size_t)(d4 * 4 + 3) * 8704;
            for (int tok = lane; tok < 136; tok += 32) {
                float4 v;
                v.x = s0[tok]; v.y = s1[tok]; v.z = s2[tok]; v.w = s3[tok];
                *reinterpret_cast<float4*>(sm + XS_OFF + tok * XSTR + d4 * 4) = v;
            }
        }
    }
    // ---- BN fold ----
    {
        float sc = bng[tid] * rsqrtf(bnv[tid] + BN_EPS);
        sm[BNS_OFF + tid] = sc;
        sm[BNB_OFF + tid] = bnbv[tid] - bnm[tid] * sc;
    }
    __syncthreads();

    const float inv_s = 0.3535533905932738f;   // 1/sqrt(8)

    // ---- Phase B: 4 head-groups of 4 heads: QKV GEMM + attention ----
    for (int g = 0; g < 4; ++g) {
        // mask bias for the 4 heads of this group
        for (int idx = tid; idx < 4 * 289; idx += 256) {
            int hl = idx / 289, r = idx - hl * 289;
            int n = r / 17, m = r - n * 17;
            int h = g * 4 + hl;
            float a = 0.5f * (adj[n * 17 + m] + adj[m * 17 + n])
                    + 0.5f * (adj2[h * 289 + n * 17 + m] + adj2[h * 289 + m * 17 + n]);
            sm[MB_OFF + idx] = (a > 0.0f) ? 0.0f : NEG_INFF;
        }
        // stage this group's qkv weights: [128 c][96 col] = 12288 floats, coalesced
        {
            const float4* src = reinterpret_cast<const float4*>(g_Wqkv3 + g * 12288);
            float4* dst = reinterpret_cast<float4*>(sm + WS_OFF);
#pragma unroll
            for (int j = 0; j < 12; ++j)
                dst[tid + j * 256] = __ldg(src + tid + j * 256);
        }
        __syncthreads();

        // QKV GEMM: thread = (17 tokens) x (one q col, one k col, one v col)
        float aq[17], ak[17], av[17];
#pragma unroll
        for (int i = 0; i < 17; ++i) { aq[i] = 0.f; ak[i] = 0.f; av[i] = 0.f; }
        {
            const float* xrow = sm + XS_OFF + tt * 17 * XSTR;
            const float* wsm = sm + WS_OFF + o32;
#pragma unroll 2
            for (int c4 = 0; c4 < 32; ++c4) {
                const float* wc = wsm + c4 * 4 * 96;
                float wq0 = wc[0],       wq1 = wc[96],       wq2 = wc[192],       wq3 = wc[288];
                float wk0 = wc[32],      wk1 = wc[96 + 32],  wk2 = wc[192 + 32],  wk3 = wc[288 + 32];
                float wv0 = wc[64],      wv1 = wc[96 + 64],  wv2 = wc[192 + 64],  wv3 = wc[288 + 64];
#pragma unroll
                for (int i = 0; i < 17; ++i) {
                    float4 xv = *reinterpret_cast<const float4*>(xrow + i * XSTR + c4 * 4);
                    aq[i] = fmaf(xv.x, wq0, aq[i]); aq[i] = fmaf(xv.y, wq1, aq[i]);
                    aq[i] = fmaf(xv.z, wq2, aq[i]); aq[i] = fmaf(xv.w, wq3, aq[i]);
                    ak[i] = fmaf(xv.x, wk0, ak[i]); ak[i] = fmaf(xv.y, wk1, ak[i]);
                    ak[i] = fmaf(xv.z, wk2, ak[i]); ak[i] = fmaf(xv.w, wk3, ak[i]);
                    av[i] = fmaf(xv.x, wv0, av[i]); av[i] = fmaf(xv.y, wv1, av[i]);
                    av[i] = fmaf(xv.z, wv2, av[i]); av[i] = fmaf(xv.w, wv3, av[i]);
                }
            }
        }
        __syncthreads();   // all weight reads done before qs/ks/vs overwrite the region
#pragma unroll
        for (int i = 0; i < 17; ++i) {
            int tok = tt * 17 + i;
            sm[QS_OFF + tok * QSTR + o32] = aq[i];
            sm[KS_OFF + tok * QSTR + o32] = ak[i];
            sm[VS_OFF + tok * QSTR + o32] = av[i];
        }
        __syncthreads();

        // Attention: one row per (tok, head-in-group): 544 rows
        for (int r = tid; r < 544; r += 256) {
            int hl  = r / 136;
            int tok = r - hl * 136;
            int tl  = tok / 17;
            int n   = tok - tl * 17;
            const float* qp = sm + QS_OFF + tok * QSTR + hl * 8;
            const float* kb = sm + KS_OFF + tl * 17 * QSTR + hl * 8;
            const float* vb = sm + VS_OFF + tl * 17 * QSTR + hl * 8;
            const float* mb = sm + MB_OFF + hl * 289 + n * 17;
            float4 q0 = *reinterpret_cast<const float4*>(qp);
            float4 q1 = *reinterpret_cast<const float4*>(qp + 4);
            float ev[17];
            float mx = -3.4e38f;
#pragma unroll
            for (int m = 0; m < 17; ++m) {
                const float* kp = kb + m * QSTR;
                float4 k0 = *reinterpret_cast<const float4*>(kp);
                float4 k1 = *reinterpret_cast<const float4*>(kp + 4);
                float d0 = q0.x * k0.x;
                d0 = fmaf(q0.y, k0.y, d0); d0 = fmaf(q0.z, k0.z, d0); d0 = fmaf(q0.w, k0.w, d0);
                d0 = fmaf(q1.x, k1.x, d0); d0 = fmaf(q1.y, k1.y, d0);
                d0 = fmaf(q1.z, k1.z, d0); d0 = fmaf(q1.w, k1.w, d0);
                ev[m] = fmaf(d0, inv_s, mb[m]);
                mx = fmaxf(mx, ev[m]);
            }
            float s = 0.f;
#pragma unroll
            for (int m = 0; m < 17; ++m) { ev[m] = __expf(ev[m] - mx); s += ev[m]; }
            float inv = __fdividef(1.0f, s);
            float4 a0 = make_float4(0.f, 0.f, 0.f, 0.f);
            float4 a1 = make_float4(0.f, 0.f, 0.f, 0.f);
#pragma unroll
            for (int m = 0; m < 17; ++m) {
                const float* vp = vb + m * QSTR;
                float4 v0 = *reinterpret_cast<const float4*>(vp);
                float4 v1 = *reinterpret_cast<const float4*>(vp + 4);
                float pm = ev[m];
                a0.x = fmaf(pm, v0.x, a0.x); a0.y = fmaf(pm, v0.y, a0.y);
                a0.z = fmaf(pm, v0.z, a0.z); a0.w = fmaf(pm, v0.w, a0.w);
                a1.x = fmaf(pm, v1.x, a1.x); a1.y = fmaf(pm, v1.y, a1.y);
                a1.z = fmaf(pm, v1.z, a1.z); a1.w = fmaf(pm, v1.w, a1.w);
            }
            a0.x *= inv; a0.y *= inv; a0.z *= inv; a0.w *= inv;
            a1.x *= inv; a1.y *= inv; a1.z *= inv; a1.w *= inv;
            float* ao = sm + AO_OFF + tok * XSTR + g * 32 + hl * 8;
            *reinterpret_cast<float4*>(ao) = a0;
            *reinterpret_cast<float4*>(ao + 4) = a1;
        }
        __syncthreads();
    }

    // ---- Phase C: conv1x1 (cat = [Xs | Ao]) + BN + ReLU, 4 chunks of 64 outputs ----
    for (int p = 0; p < 4; ++p) {
        const int ob = p * 64;
        float acc0[17], acc1[17];
#pragma unroll
        for (int i = 0; i < 17; ++i) { acc0[i] = 0.f; acc1[i] = 0.f; }
        const float* xrow = sm + XS_OFF + tt * 17 * XSTR;
        const float* arow = sm + AO_OFF + tt * 17 * XSTR;

        for (int half = 0; half < 2; ++half) {
            // stage Wc half: [128 c][64 col] = 8192 floats, coalesced from g_WcT[c][o]
            {
                float4* dst = reinterpret_cast<float4*>(sm + WS_OFF);
#pragma unroll
                for (int j = 0; j < 8; ++j) {
                    int j4 = tid + j * 256;            // 0..2047
                    int c = j4 >> 4, olq = j4 & 15;    // 16 float4 per c-row
                    dst[j4] = __ldg(reinterpret_cast<const float4*>(
                                    g_WcT + (half * 128 + c) * 256 + ob) + olq);
                }
            }
            __syncthreads();
            const float* src = half ? arow : xrow;
            const float* wsm = sm + WS_OFF + o32;
#pragma unroll 2
            for (int c4 = 0; c4 < 32; ++c4) {
                const float* wc = wsm + c4 * 4 * 64;
                float wa0 = wc[0],  wa1 = wc[64],      wa2 = wc[128],      wa3 = wc[192];
                float wb0 = wc[32], wb1 = wc[64 + 32], wb2 = wc[128 + 32], wb3 = wc[192 + 32];
#pragma unroll
                for (int i = 0; i < 17; ++i) {
                    float4 xv = *reinterpret_cast<const float4*>(src + i * XSTR + c4 * 4);
                    acc0[i] = fmaf(xv.x, wa0, acc0[i]); acc0[i] = fmaf(xv.y, wa1, acc0[i]);
                    acc0[i] = fmaf(xv.z, wa2, acc0[i]); acc0[i] = fmaf(xv.w, wa3, acc0[i]);
                    acc1[i] = fmaf(xv.x, wb0, acc1[i]); acc1[i] = fmaf(xv.y, wb1, acc1[i]);
                    acc1[i] = fmaf(xv.z, wb2, acc1[i]); acc1[i] = fmaf(xv.w, wb3, acc1[i]);
                }
            }
            __syncthreads();   // weight reads done before region is rewritten
        }

        // BN + ReLU into staging buffer Ys[64][137]
        {
            int oa = ob + o32, oc = oa + 32;
            float s0 = sm[BNS_OFF + oa], h0 = sm[BNB_OFF + oa];
            float s1 = sm[BNS_OFF + oc], h1 = sm[BNB_OFF + oc];
#pragma unroll
            for (int i = 0; i < 17; ++i) {
                int tok = tt * 17 + i;
                sm[YS_OFF + o32 * 137 + tok]        = fmaxf(fmaf(acc0[i], s0, h0), 0.0f);
                sm[YS_OFF + (o32 + 32) * 137 + tok] = fmaxf(fmaf(acc1[i], s1, h1), 0.0f);
            }
        }
        __syncthreads();
        // coalesced store: out[b][o][t][n] = out[(b*256+o)*8704 + t*17+n]
        {
            float* ob_ptr = out + (size_t)(b * 256 + ob) * 8704 + (size_t)t0 * 17;
            for (int idx = tid; idx < 64 * 136; idx += 256) {
                int ol = idx / 136;
                int tok = idx - ol * 136;
                ob_ptr[(size_t)ol * 8704 + tok] = sm[YS_OFF + ol * 137 + tok];
            }
        }
        __syncthreads();
    }
}

// ---------------- launch ----------------
extern "C" void kernel_launch(void* const* d_in, const int* in_sizes, int n_in,
                              void* d_out, int out_size) {
    const float* x      = (const float*)d_in[0];
    const float* adj    = (const float*)d_in[1];
    const float* Wq     = (const float*)d_in[2];
    const float* Wk     = (const float*)d_in[3];
    const float* Wv     = (const float*)d_in[4];
    const float* adj2   = (const float*)d_in[5];
    const float* convw  = (const float*)d_in[6];
    const float* bng    = (const float*)d_in[7];
    const float* bnb    = (const float*)d_in[8];
    const float* bnm    = (const float*)d_in[9];
    const float* bnv    = (const float*)d_in[10];
    float* out = (float*)d_out;

    cudaFuncSetAttribute(gab_kernel, cudaFuncAttributeMaxDynamicSharedMemorySize, SMEM_BYTES);

    prep_kernel<<<(4 * 128 * 96 + 256 * 256 + 255) / 256, 256>>>(Wq, Wk, Wv, convw);
    gab_kernel<<<2048, 256, SMEM_BYTES>>>(x, adj, adj2, bng, bnb, bnm, bnv, out);
}